// round 1
// baseline (speedup 1.0000x reference)
#include <cuda_runtime.h>
#include <math.h>

#define Bb   2
#define Ss   2048
#define Hh   1024
#define NHd  16
#define Dd   64
#define Mtok (Bb*Ss)          // 4096 tokens

// Scratch: qlin,klin,vlin, qT,kT,vT, attn  — 7 planes of [4096,1024] f32
__device__ float g_scratch[(size_t)7 * Mtok * Hh];

// ---------------------------------------------------------------------------
// Tiled SGEMM:  C[M,N] = A[M,K] @ W[N,K]^T + bias[N]
// BM=BN=64, BK=32, 256 threads, 4x4 microtile per thread.
// ---------------------------------------------------------------------------
#define BM 64
#define BN 64
#define BK 32
__global__ __launch_bounds__(256)
void gemm_bias_kernel(const float* __restrict__ A, const float* __restrict__ W,
                      const float* __restrict__ bias, float* __restrict__ C,
                      int M, int N, int K)
{
    __shared__ float As[BK][BM + 4];
    __shared__ float Ws[BK][BN + 4];
    const int tid = threadIdx.x;
    const int bm = blockIdx.y * BM, bn = blockIdx.x * BN;
    const int tx = tid & 15, ty = tid >> 4;
    float acc[4][4] = {};

    for (int k0 = 0; k0 < K; k0 += BK) {
        #pragma unroll
        for (int t = 0; t < 2; t++) {
            int idx = tid + t * 256;          // 512 float4 per tile
            int r  = idx >> 3;                // 0..63
            int c4 = (idx & 7) << 2;          // 0,4,...,28
            float4 va = *(const float4*)&A[(size_t)(bm + r) * K + k0 + c4];
            As[c4 + 0][r] = va.x; As[c4 + 1][r] = va.y;
            As[c4 + 2][r] = va.z; As[c4 + 3][r] = va.w;
            float4 vw = *(const float4*)&W[(size_t)(bn + r) * K + k0 + c4];
            Ws[c4 + 0][r] = vw.x; Ws[c4 + 1][r] = vw.y;
            Ws[c4 + 2][r] = vw.z; Ws[c4 + 3][r] = vw.w;
        }
        __syncthreads();
        #pragma unroll
        for (int k = 0; k < BK; k++) {
            float a[4], b[4];
            *(float4*)a = *(const float4*)&As[k][ty * 4];
            *(float4*)b = *(const float4*)&Ws[k][tx * 4];
            #pragma unroll
            for (int i = 0; i < 4; i++)
                #pragma unroll
                for (int j = 0; j < 4; j++)
                    acc[i][j] = fmaf(a[i], b[j], acc[i][j]);
        }
        __syncthreads();
    }

    float4 bv = *(const float4*)&bias[bn + tx * 4];
    #pragma unroll
    for (int i = 0; i < 4; i++) {
        int row = bm + ty * 4 + i;
        float4 o;
        o.x = acc[i][0] + bv.x; o.y = acc[i][1] + bv.y;
        o.z = acc[i][2] + bv.z; o.w = acc[i][3] + bv.w;
        *(float4*)&C[(size_t)row * N + bn + tx * 4] = o;
    }
}

// ---------------------------------------------------------------------------
// RMSNorm (over full H=1024) + RoPE for q,k; transpose q,k,v into [B,NH,S,D]
// One block per token, 256 threads.
// ---------------------------------------------------------------------------
__global__ __launch_bounds__(256)
void normrope_kernel(const float* __restrict__ qlin, const float* __restrict__ klin,
                     const float* __restrict__ vlin,
                     const float* __restrict__ cosT, const float* __restrict__ sinT,
                     const float* __restrict__ w,
                     float* __restrict__ qo, float* __restrict__ ko, float* __restrict__ vo)
{
    const int t = blockIdx.x;          // token 0..4095
    const int b = t >> 11;             // batch
    const int s = t & 2047;            // seq pos
    const int tid = threadIdx.x;

    __shared__ float sq[1024], sk[1024];
    __shared__ float red[16];
    __shared__ float rqs, rks;

    float sumq = 0.f, sumk = 0.f;
    for (int i = tid; i < 1024; i += 256) {
        float x = qlin[(size_t)t * 1024 + i]; sq[i] = x; sumq += x * x;
        float y = klin[(size_t)t * 1024 + i]; sk[i] = y; sumk += y * y;
    }
    #pragma unroll
    for (int off = 16; off > 0; off >>= 1) {
        sumq += __shfl_down_sync(0xffffffffu, sumq, off);
        sumk += __shfl_down_sync(0xffffffffu, sumk, off);
    }
    if ((tid & 31) == 0) { red[tid >> 5] = sumq; red[8 + (tid >> 5)] = sumk; }
    __syncthreads();
    if (tid == 0) {
        float a = 0.f, c = 0.f;
        #pragma unroll
        for (int i2 = 0; i2 < 8; i2++) { a += red[i2]; c += red[8 + i2]; }
        rqs = rsqrtf(a * (1.0f / 1024.0f) + 1e-6f);
        rks = rsqrtf(c * (1.0f / 1024.0f) + 1e-6f);
    }
    __syncthreads();
    const float rq = rqs, rk = rks;

    for (int i = tid; i < 1024; i += 256) {
        int h = i >> 6, d = i & 63;
        float cs = cosT[s * 64 + d], sn = sinT[s * 64 + d];
        int   pi = (d < 32) ? i + 32 : i - 32;
        float sign = (d < 32) ? -1.f : 1.f;
        float wv = w[i], wp = w[pi];
        float qv = sq[i] * rq * wv, qp = sq[pi] * rq * wp;
        float kv = sk[i] * rk * wv, kp = sk[pi] * rk * wp;
        size_t oidx = ((size_t)(b * NHd + h) * Ss + s) * Dd + d;
        qo[oidx] = qv * cs + sign * qp * sn;
        ko[oidx] = kv * cs + sign * kp * sn;
        vo[oidx] = vlin[(size_t)t * 1024 + i];
    }
}

// ---------------------------------------------------------------------------
// Flash-style attention (fp32, online softmax). One thread per query row.
// 64 queries per block, iterate K/V in 64-key tiles. Scores get +1.0 bias on
// the lower triangle (NOT a mask — all keys participate in the softmax).
// Output written directly in [B,S,H] token-major layout.
// ---------------------------------------------------------------------------
__global__ __launch_bounds__(64)
void flash_kernel(const float* __restrict__ q, const float* __restrict__ k,
                  const float* __restrict__ v, float* __restrict__ out)
{
    const int bh  = blockIdx.y;                   // 0..31  (b*16 + h)
    const int row = blockIdx.x * 64 + threadIdx.x; // query s-index
    const float* qb = q + (size_t)bh * Ss * Dd;
    const float* kb = k + (size_t)bh * Ss * Dd;
    const float* vb = v + (size_t)bh * Ss * Dd;

    __shared__ float ks[64][64];
    __shared__ float vs[64][64];

    const float inv_scale = 0.125f;               // 1/sqrt(64), folded into q
    float qr[64];
    #pragma unroll
    for (int d = 0; d < 64; d += 4) {
        float4 t = *(const float4*)&qb[(size_t)row * 64 + d];
        qr[d] = t.x * inv_scale; qr[d + 1] = t.y * inv_scale;
        qr[d + 2] = t.z * inv_scale; qr[d + 3] = t.w * inv_scale;
    }
    float o[64];
    #pragma unroll
    for (int d = 0; d < 64; d++) o[d] = 0.f;
    float m = -1e30f, l = 0.f;

    for (int kt = 0; kt < Ss; kt += 64) {
        __syncthreads();
        #pragma unroll
        for (int t = 0; t < 16; t++) {            // 1024 float4 total, coalesced
            int idx = t * 64 + threadIdx.x;
            int r = idx >> 4, c = (idx & 15) << 2;
            *(float4*)&ks[r][c] = *(const float4*)&kb[(size_t)(kt + r) * 64 + c];
            *(float4*)&vs[r][c] = *(const float4*)&vb[(size_t)(kt + r) * 64 + c];
        }
        __syncthreads();

        #pragma unroll 1
        for (int jc = 0; jc < 64; jc += 16) {     // keep code size bounded
            float sc[16];
            float mt = m;
            #pragma unroll
            for (int j = 0; j < 16; j++) {
                int jj = jc + j;
                float s0 = 0.f, s1 = 0.f, s2 = 0.f, s3 = 0.f;
                #pragma unroll
                for (int d = 0; d < 64; d += 16) {
                    float4 a0 = *(const float4*)&ks[jj][d + 0];
                    float4 a1 = *(const float4*)&ks[jj][d + 4];
                    float4 a2 = *(const float4*)&ks[jj][d + 8];
                    float4 a3 = *(const float4*)&ks[jj][d + 12];
                    s0 = fmaf(qr[d+0], a0.x, fmaf(qr[d+1], a0.y, fmaf(qr[d+2], a0.z, fmaf(qr[d+3], a0.w, s0))));
                    s1 = fmaf(qr[d+4], a1.x, fmaf(qr[d+5], a1.y, fmaf(qr[d+6], a1.z, fmaf(qr[d+7], a1.w, s1))));
                    s2 = fmaf(qr[d+8], a2.x, fmaf(qr[d+9], a2.y, fmaf(qr[d+10], a2.z, fmaf(qr[d+11], a2.w, s2))));
                    s3 = fmaf(qr[d+12], a3.x, fmaf(qr[d+13], a3.y, fmaf(qr[d+14], a3.z, fmaf(qr[d+15], a3.w, s3))));
                }
                float sv = (s0 + s1) + (s2 + s3);
                sv += ((kt + jj) <= row) ? 1.0f : 0.0f;   // +tril(ones) bias
                sc[j] = sv;
                mt = fmaxf(mt, sv);
            }
            float alpha = __expf(m - mt);
            m = mt;
            float psum = 0.f;
            #pragma unroll
            for (int j = 0; j < 16; j++) { sc[j] = __expf(sc[j] - m); psum += sc[j]; }
            l = l * alpha + psum;
            #pragma unroll
            for (int d = 0; d < 64; d++) o[d] *= alpha;
            #pragma unroll
            for (int j = 0; j < 16; j++) {
                float p = sc[j];
                #pragma unroll
                for (int d = 0; d < 64; d += 4) {
                    float4 vv = *(const float4*)&vs[jc + j][d];
                    o[d]     = fmaf(p, vv.x, o[d]);
                    o[d + 1] = fmaf(p, vv.y, o[d + 1]);
                    o[d + 2] = fmaf(p, vv.z, o[d + 2]);
                    o[d + 3] = fmaf(p, vv.w, o[d + 3]);
                }
            }
        }
    }

    const float invl = 1.f / l;
    const int b = bh >> 4, h = bh & 15;
    float* ob = out + ((size_t)(b * Ss + row)) * Hh + h * Dd;   // token-major
    #pragma unroll
    for (int d = 0; d < 64; d += 4) {
        float4 t;
        t.x = o[d] * invl; t.y = o[d + 1] * invl;
        t.z = o[d + 2] * invl; t.w = o[d + 3] * invl;
        *(float4*)&ob[d] = t;
    }
}

// ---------------------------------------------------------------------------
extern "C" void kernel_launch(void* const* d_in, const int* in_sizes, int n_in,
                              void* d_out, int out_size)
{
    const float* hs   = (const float*)d_in[0];
    const float* cosT = (const float*)d_in[1];
    const float* sinT = (const float*)d_in[2];
    const float* Wq   = (const float*)d_in[3];
    const float* bq   = (const float*)d_in[4];
    const float* Wk   = (const float*)d_in[5];
    const float* bk   = (const float*)d_in[6];
    const float* Wv   = (const float*)d_in[7];
    const float* bv   = (const float*)d_in[8];
    const float* Wo   = (const float*)d_in[9];
    const float* bo   = (const float*)d_in[10];
    const float* rw   = (const float*)d_in[11];
    float* out = (float*)d_out;

    float* scratch = nullptr;
    cudaGetSymbolAddress((void**)&scratch, g_scratch);
    const size_t SZ = (size_t)Mtok * Hh;
    float* qlin = scratch;
    float* klin = scratch + 1 * SZ;
    float* vlin = scratch + 2 * SZ;
    float* qT   = scratch + 3 * SZ;
    float* kT   = scratch + 4 * SZ;
    float* vT   = scratch + 5 * SZ;
    float* attn = scratch + 6 * SZ;

    dim3 gg(Hh / BN, Mtok / BM);
    gemm_bias_kernel<<<gg, 256>>>(hs, Wq, bq, qlin, Mtok, Hh, Hh);
    gemm_bias_kernel<<<gg, 256>>>(hs, Wk, bk, klin, Mtok, Hh, Hh);
    gemm_bias_kernel<<<gg, 256>>>(hs, Wv, bv, vlin, Mtok, Hh, Hh);

    normrope_kernel<<<Mtok, 256>>>(qlin, klin, vlin, cosT, sinT, rw, qT, kT, vT);

    dim3 fg(Ss / 64, Bb * NHd);
    flash_kernel<<<fg, 64>>>(qT, kT, vT, attn);

    gemm_bias_kernel<<<gg, 256>>>(attn, Wo, bo, out, Mtok, Hh, Hh);
}

// round 2
// speedup vs baseline: 1.6012x; 1.6012x over previous
#include <cuda_runtime.h>
#include <mma.h>
#include <math.h>

using namespace nvcuda;

#define Bb    2
#define SEQ   2048
#define Hh    1024
#define NHd   16
#define Dd    64
#define Mtok  4096

// Scratch: qlin,klin,vlin, qT,kT,vT, attn  — 7 planes of [4096,1024] f32
__device__ float g_scratch[(size_t)7 * Mtok * Hh];

template <class Frag>
__device__ __forceinline__ void frag_to_tf32(Frag& f) {
    #pragma unroll
    for (int i = 0; i < f.num_elements; i++)
        f.x[i] = wmma::__float_to_tf32(f.x[i]);
}

// ---------------------------------------------------------------------------
// tf32 GEMM:  C[M,N] = A[M,K] @ W[N,K]^T   (no bias — folded downstream)
// 128x64 block tile, BK=32, 256 threads, 8 warps of 32x32.
// ---------------------------------------------------------------------------
#define GBM 128
#define GBN 64
#define GBK 32
#define GLD 40   // padded leading dim (multiple of 8)

__global__ __launch_bounds__(256)
void gemm_tf32_kernel(const float* __restrict__ A, const float* __restrict__ W,
                      float* __restrict__ C, int M, int N, int K)
{
    __shared__ __align__(16) float As[GBM * GLD];
    __shared__ __align__(16) float Wsm[GBN * GLD];
    const int tid = threadIdx.x;
    const int bm = blockIdx.y * GBM, bn = blockIdx.x * GBN;
    const int w  = tid >> 5;
    const int wr = w & 3;          // 0..3 row warps (32 rows each)
    const int wc = w >> 2;         // 0..1 col warps (32 cols each)

    wmma::fragment<wmma::accumulator, 16, 16, 8, float> acc[2][2];
    #pragma unroll
    for (int i = 0; i < 2; i++)
        #pragma unroll
        for (int j = 0; j < 2; j++) wmma::fill_fragment(acc[i][j], 0.0f);

    for (int k0 = 0; k0 < K; k0 += GBK) {
        // A tile: 128x32 = 1024 float4
        #pragma unroll
        for (int t = 0; t < 4; t++) {
            int idx = tid + t * 256;
            int r = idx >> 3, c4 = (idx & 7) << 2;
            float4 v = *(const float4*)&A[(size_t)(bm + r) * K + k0 + c4];
            *(float4*)&As[r * GLD + c4] = v;        // GLD*4=160B, 16B-aligned
        }
        // W tile: 64x32 = 512 float4
        #pragma unroll
        for (int t = 0; t < 2; t++) {
            int idx = tid + t * 256;
            int r = idx >> 3, c4 = (idx & 7) << 2;
            float4 v = *(const float4*)&W[(size_t)(bn + r) * K + k0 + c4];
            *(float4*)&Wsm[r * GLD + c4] = v;
        }
        __syncthreads();

        #pragma unroll
        for (int kk = 0; kk < 4; kk++) {
            const int kd = kk * 8;
            wmma::fragment<wmma::matrix_a, 16, 16, 8, wmma::precision::tf32, wmma::row_major> a0, a1;
            wmma::fragment<wmma::matrix_b, 16, 16, 8, wmma::precision::tf32, wmma::col_major> b0, b1;
            wmma::load_matrix_sync(a0, &As[(wr * 32     ) * GLD + kd], GLD);
            wmma::load_matrix_sync(a1, &As[(wr * 32 + 16) * GLD + kd], GLD);
            wmma::load_matrix_sync(b0, &Wsm[(wc * 32     ) * GLD + kd], GLD);
            wmma::load_matrix_sync(b1, &Wsm[(wc * 32 + 16) * GLD + kd], GLD);
            frag_to_tf32(a0); frag_to_tf32(a1);
            frag_to_tf32(b0); frag_to_tf32(b1);
            wmma::mma_sync(acc[0][0], a0, b0, acc[0][0]);
            wmma::mma_sync(acc[0][1], a0, b1, acc[0][1]);
            wmma::mma_sync(acc[1][0], a1, b0, acc[1][0]);
            wmma::mma_sync(acc[1][1], a1, b1, acc[1][1]);
        }
        __syncthreads();
    }

    #pragma unroll
    for (int i = 0; i < 2; i++)
        #pragma unroll
        for (int j = 0; j < 2; j++) {
            int row = bm + wr * 32 + i * 16;
            int col = bn + wc * 32 + j * 16;
            wmma::store_matrix_sync(&C[(size_t)row * N + col], acc[i][j], N, wmma::mem_row_major);
        }
}

// ---------------------------------------------------------------------------
// RMSNorm + bias + RoPE for q,k; transpose q,k,v into [B,NH,S,D]
// ---------------------------------------------------------------------------
__global__ __launch_bounds__(256)
void normrope_kernel(const float* __restrict__ qlin, const float* __restrict__ klin,
                     const float* __restrict__ vlin,
                     const float* __restrict__ bq, const float* __restrict__ bk,
                     const float* __restrict__ bv,
                     const float* __restrict__ cosT, const float* __restrict__ sinT,
                     const float* __restrict__ w,
                     float* __restrict__ qo, float* __restrict__ ko, float* __restrict__ vo)
{
    const int t = blockIdx.x;
    const int b = t >> 11;
    const int s = t & 2047;
    const int tid = threadIdx.x;

    __shared__ float sq[1024], sk[1024];
    __shared__ float red[16];
    __shared__ float rqs, rks;

    float sumq = 0.f, sumk = 0.f;
    for (int i = tid; i < 1024; i += 256) {
        float x = qlin[(size_t)t * 1024 + i] + bq[i]; sq[i] = x; sumq += x * x;
        float y = klin[(size_t)t * 1024 + i] + bk[i]; sk[i] = y; sumk += y * y;
    }
    #pragma unroll
    for (int off = 16; off > 0; off >>= 1) {
        sumq += __shfl_down_sync(0xffffffffu, sumq, off);
        sumk += __shfl_down_sync(0xffffffffu, sumk, off);
    }
    if ((tid & 31) == 0) { red[tid >> 5] = sumq; red[8 + (tid >> 5)] = sumk; }
    __syncthreads();
    if (tid == 0) {
        float a = 0.f, c = 0.f;
        #pragma unroll
        for (int i2 = 0; i2 < 8; i2++) { a += red[i2]; c += red[8 + i2]; }
        rqs = rsqrtf(a * (1.0f / 1024.0f) + 1e-6f);
        rks = rsqrtf(c * (1.0f / 1024.0f) + 1e-6f);
    }
    __syncthreads();
    const float rq = rqs, rk = rks;

    for (int i = tid; i < 1024; i += 256) {
        int h = i >> 6, d = i & 63;
        float cs = cosT[s * 64 + d], sn = sinT[s * 64 + d];
        int   pi = (d < 32) ? i + 32 : i - 32;
        float sign = (d < 32) ? -1.f : 1.f;
        float wv = w[i], wp = w[pi];
        float qv = sq[i] * rq * wv, qp = sq[pi] * rq * wp;
        float kv = sk[i] * rk * wv, kp = sk[pi] * rk * wp;
        size_t oidx = ((size_t)(b * NHd + h) * SEQ + s) * Dd + d;
        qo[oidx] = qv * cs + sign * qp * sn;
        ko[oidx] = kv * cs + sign * kp * sn;
        vo[oidx] = vlin[(size_t)t * 1024 + i] + bv[i];
    }
}

// ---------------------------------------------------------------------------
// Flash attention with tf32 wmma. 1 block = 64 queries x 1 (b,h). 4 warps.
// Warp w owns rows [w*16, w*16+16) for MMA, softmax and O update — so only
// the K/V smem tiles need block-level barriers (2 syncthreads per tile).
// Scores get +1.0 bias on the lower triangle (NOT a mask).
// ---------------------------------------------------------------------------
#define FLD   72            // padded row stride for Ks/Vs/Ss (mult of 8)
#define FOLD  68            // padded row stride for Os
#define FK_ELEMS (64 * FLD) // 4608

__global__ __launch_bounds__(128)
void flash_tf32_kernel(const float* __restrict__ q, const float* __restrict__ k,
                       const float* __restrict__ v, float* __restrict__ out)
{
    extern __shared__ __align__(16) float sm[];
    float* Ks   = sm;
    float* Vs   = sm + FK_ELEMS;
    float* Sp   = sm + 2 * FK_ELEMS;
    float* Os   = sm + 3 * FK_ELEMS;
    float* mrow = sm + 3 * FK_ELEMS + 64 * FOLD;
    float* lrow = mrow + 64;
    float* arow = lrow + 64;

    const int tid = threadIdx.x;
    const int w   = tid >> 5;
    const int bh  = blockIdx.y;            // b*16 + h
    const int qt  = blockIdx.x;            // query tile (64 rows)
    const float* kb = k + (size_t)bh * SEQ * Dd;
    const float* vb = v + (size_t)bh * SEQ * Dd;

    // init O, m, l
    for (int i = tid; i < 64 * FOLD; i += 128) Os[i] = 0.f;
    if (tid < 64) { mrow[tid] = -1e30f; lrow[tid] = 0.f; }

    // Q fragments (registers), scaled by 1/sqrt(D)=0.125, tf32-rounded
    wmma::fragment<wmma::matrix_a, 16, 16, 8, wmma::precision::tf32, wmma::row_major> qfrag[8];
    {
        const float* qptr = q + ((size_t)bh * SEQ + qt * 64 + w * 16) * Dd;
        #pragma unroll
        for (int kk = 0; kk < 8; kk++) {
            wmma::load_matrix_sync(qfrag[kk], qptr + kk * 8, Dd);
            #pragma unroll
            for (int e = 0; e < qfrag[kk].num_elements; e++)
                qfrag[kk].x[e] = wmma::__float_to_tf32(qfrag[kk].x[e] * 0.125f);
        }
    }

    const int row  = tid >> 1;             // 0..63 (warp w handles rows w*16..)
    const int half = tid & 1;              // 32-col half
    const int qrow = qt * 64 + row;        // global query index

    for (int kt = 0; kt < SEQ; kt += 64) {
        __syncthreads();                   // prior readers of Ks/Vs done
        #pragma unroll
        for (int t = 0; t < 8; t++) {      // 1024 float4 per tile
            int i = t * 128 + tid;
            int r = i >> 4, c = (i & 15) << 2;
            *(float4*)&Ks[r * FLD + c] = *(const float4*)&kb[(size_t)(kt + r) * Dd + c];
            *(float4*)&Vs[r * FLD + c] = *(const float4*)&vb[(size_t)(kt + r) * Dd + c];
        }
        __syncthreads();

        // ---- S = Q @ K^T (warp strip 16x64) ----
        wmma::fragment<wmma::accumulator, 16, 16, 8, float> sfr[4];
        #pragma unroll
        for (int nt = 0; nt < 4; nt++) wmma::fill_fragment(sfr[nt], 0.0f);
        #pragma unroll
        for (int kk = 0; kk < 8; kk++) {
            const int kd = kk * 8;
            #pragma unroll
            for (int nt = 0; nt < 4; nt++) {
                wmma::fragment<wmma::matrix_b, 16, 16, 8, wmma::precision::tf32, wmma::col_major> bfr;
                wmma::load_matrix_sync(bfr, &Ks[(nt * 16) * FLD + kd], FLD);
                frag_to_tf32(bfr);
                wmma::mma_sync(sfr[nt], qfrag[kk], bfr, sfr[nt]);
            }
        }
        #pragma unroll
        for (int nt = 0; nt < 4; nt++)
            wmma::store_matrix_sync(&Sp[(w * 16) * FLD + nt * 16], sfr[nt], FLD, wmma::mem_row_major);
        __syncwarp();

        // ---- softmax on own rows (2 threads per row, 32 cols each) ----
        {
            float* srow = &Sp[row * FLD + half * 32];
            float vals[32];
            float mx = -1e30f;
            #pragma unroll
            for (int c = 0; c < 32; c++) {
                float s = srow[c];
                s += ((kt + half * 32 + c) <= qrow) ? 1.0f : 0.0f;   // +tril bias
                vals[c] = s;
                mx = fmaxf(mx, s);
            }
            mx = fmaxf(mx, __shfl_xor_sync(0xffffffffu, mx, 1));
            float mold = mrow[row];
            float mnew = fmaxf(mold, mx);
            float psum = 0.f;
            #pragma unroll
            for (int c = 0; c < 32; c++) {
                float p = __expf(vals[c] - mnew);
                srow[c] = p;
                psum += p;
            }
            psum += __shfl_xor_sync(0xffffffffu, psum, 1);
            if (half == 0) {
                float alpha = __expf(mold - mnew);
                arow[row] = alpha;
                mrow[row] = mnew;
                lrow[row] = lrow[row] * alpha + psum;
            }
        }
        __syncwarp();

        // ---- PV = P @ V (warp strip 16x64) ----
        wmma::fragment<wmma::accumulator, 16, 16, 8, float> pv[4];
        #pragma unroll
        for (int nt = 0; nt < 4; nt++) wmma::fill_fragment(pv[nt], 0.0f);
        #pragma unroll
        for (int kk = 0; kk < 8; kk++) {
            wmma::fragment<wmma::matrix_a, 16, 16, 8, wmma::precision::tf32, wmma::row_major> afr;
            wmma::load_matrix_sync(afr, &Sp[(w * 16) * FLD + kk * 8], FLD);
            frag_to_tf32(afr);
            #pragma unroll
            for (int nt = 0; nt < 4; nt++) {
                wmma::fragment<wmma::matrix_b, 16, 16, 8, wmma::precision::tf32, wmma::row_major> vfr;
                wmma::load_matrix_sync(vfr, &Vs[(kk * 8) * FLD + nt * 16], FLD);
                frag_to_tf32(vfr);
                wmma::mma_sync(pv[nt], afr, vfr, pv[nt]);
            }
        }
        // overwrite own P rows with PV result
        #pragma unroll
        for (int nt = 0; nt < 4; nt++)
            wmma::store_matrix_sync(&Sp[(w * 16) * FLD + nt * 16], pv[nt], FLD, wmma::mem_row_major);
        __syncwarp();

        // ---- O = O*alpha + PV on own rows ----
        {
            float alpha = arow[row];
            float* orow = &Os[row * FOLD + half * 32];
            float* prow = &Sp[row * FLD + half * 32];
            #pragma unroll
            for (int c = 0; c < 32; c += 4) {
                float4 o4 = *(float4*)&orow[c];
                float4 p4 = *(float4*)&prow[c];
                o4.x = o4.x * alpha + p4.x; o4.y = o4.y * alpha + p4.y;
                o4.z = o4.z * alpha + p4.z; o4.w = o4.w * alpha + p4.w;
                *(float4*)&orow[c] = o4;
            }
        }
    }

    __syncwarp();
    // epilogue: divide by l, write token-major [B,S,H]
    {
        const int b = bh >> 4, h = bh & 15;
        float invl = 1.f / lrow[row];
        const float* orow = &Os[row * FOLD + half * 32];
        float* dst = out + ((size_t)(b * SEQ + qt * 64 + row)) * Hh + h * Dd + half * 32;
        #pragma unroll
        for (int c = 0; c < 32; c += 4) {
            float4 t = *(const float4*)&orow[c];
            t.x *= invl; t.y *= invl; t.z *= invl; t.w *= invl;
            *(float4*)&dst[c] = t;
        }
    }
}

// ---------------------------------------------------------------------------
__global__ __launch_bounds__(256)
void add_bias_kernel(float* __restrict__ out, const float* __restrict__ bo)
{
    int idx = blockIdx.x * 256 + threadIdx.x;
    out[idx] += bo[idx & (Hh - 1)];
}

// ---------------------------------------------------------------------------
extern "C" void kernel_launch(void* const* d_in, const int* in_sizes, int n_in,
                              void* d_out, int out_size)
{
    const float* hs   = (const float*)d_in[0];
    const float* cosT = (const float*)d_in[1];
    const float* sinT = (const float*)d_in[2];
    const float* Wq   = (const float*)d_in[3];
    const float* bq   = (const float*)d_in[4];
    const float* Wk   = (const float*)d_in[5];
    const float* bk   = (const float*)d_in[6];
    const float* Wv   = (const float*)d_in[7];
    const float* bv   = (const float*)d_in[8];
    const float* Wo   = (const float*)d_in[9];
    const float* bo   = (const float*)d_in[10];
    const float* rw   = (const float*)d_in[11];
    float* out = (float*)d_out;

    float* scratch = nullptr;
    cudaGetSymbolAddress((void**)&scratch, g_scratch);
    const size_t SZ = (size_t)Mtok * Hh;
    float* qlin = scratch;
    float* klin = scratch + 1 * SZ;
    float* vlin = scratch + 2 * SZ;
    float* qT   = scratch + 3 * SZ;
    float* kT   = scratch + 4 * SZ;
    float* vT   = scratch + 5 * SZ;
    float* attn = scratch + 6 * SZ;

    const int flash_smem = (3 * FK_ELEMS + 64 * FOLD + 192) * (int)sizeof(float);
    cudaFuncSetAttribute(flash_tf32_kernel,
                         cudaFuncAttributeMaxDynamicSharedMemorySize, flash_smem);

    dim3 gg(Hh / GBN, Mtok / GBM);
    gemm_tf32_kernel<<<gg, 256>>>(hs, Wq, qlin, Mtok, Hh, Hh);
    gemm_tf32_kernel<<<gg, 256>>>(hs, Wk, klin, Mtok, Hh, Hh);
    gemm_tf32_kernel<<<gg, 256>>>(hs, Wv, vlin, Mtok, Hh, Hh);

    normrope_kernel<<<Mtok, 256>>>(qlin, klin, vlin, bq, bk, bv,
                                   cosT, sinT, rw, qT, kT, vT);

    dim3 fg(SEQ / 64, Bb * NHd);
    flash_tf32_kernel<<<fg, 128, flash_smem>>>(qT, kT, vT, attn);

    gemm_tf32_kernel<<<gg, 256>>>(attn, Wo, out, Mtok, Hh, Hh);
    add_bias_kernel<<<(Mtok * Hh) / 256, 256>>>(out, bo);
}

// round 3
// speedup vs baseline: 1.7764x; 1.1094x over previous
#include <cuda_runtime.h>
#include <mma.h>
#include <math.h>

using namespace nvcuda;

#define Bb    2
#define SEQ   2048
#define Hh    1024
#define NHd   16
#define Dd    64
#define Mtok  4096

// Scratch: qlin,klin,vlin, qT,kT,vT, attn
__device__ float g_scratch[(size_t)7 * Mtok * Hh];

template <class Frag>
__device__ __forceinline__ void frag_to_tf32(Frag& f) {
    #pragma unroll
    for (int i = 0; i < f.num_elements; i++)
        f.x[i] = wmma::__float_to_tf32(f.x[i]);
}

__device__ __forceinline__ void cp_async16(float* smem, const float* gmem) {
    unsigned saddr = (unsigned)__cvta_generic_to_shared(smem);
    asm volatile("cp.async.cg.shared.global [%0], [%1], 16;\n" :: "r"(saddr), "l"(gmem));
}
__device__ __forceinline__ void cp_commit() { asm volatile("cp.async.commit_group;\n"); }
template <int N>
__device__ __forceinline__ void cp_wait() { asm volatile("cp.async.wait_group %0;\n" :: "n"(N)); }

// ---------------------------------------------------------------------------
// tf32 GEMM: C[M,N] = A[M,K] @ W[N,K]^T.  128x128 tile, BK=32,
// 2-stage cp.async double buffer, 256 threads, 8 warps of 32x64.
// ---------------------------------------------------------------------------
#define GBM 128
#define GBN 128
#define GBK 32
#define GLD 40
#define GST (GBM * GLD)      // floats per A-stage (= B-stage)

__global__ __launch_bounds__(256)
void gemm_tf32_kernel(const float* __restrict__ A, const float* __restrict__ W,
                      float* __restrict__ C, int M, int N, int K)
{
    extern __shared__ __align__(16) float gsm[];
    float* As = gsm;                 // [2][GST]
    float* Bs = gsm + 2 * GST;       // [2][GST]

    const int tid = threadIdx.x;
    const int bm = blockIdx.y * GBM, bn = blockIdx.x * GBN;
    const int w  = tid >> 5;
    const int wr = w & 3;            // 4 row warps (32 rows)
    const int wc = w >> 2;           // 2 col warps (64 cols)

    wmma::fragment<wmma::accumulator, 16, 16, 8, float> acc[2][4];
    #pragma unroll
    for (int i = 0; i < 2; i++)
        #pragma unroll
        for (int j = 0; j < 4; j++) wmma::fill_fragment(acc[i][j], 0.0f);

    const int lr = tid >> 3;               // 0..31
    const int lc4 = (tid & 7) << 2;        // 0..28

    // prefetch stage 0
    {
        #pragma unroll
        for (int t = 0; t < 4; t++) {
            int r = lr + t * 32;
            cp_async16(&As[r * GLD + lc4], &A[(size_t)(bm + r) * K + lc4]);
            cp_async16(&Bs[r * GLD + lc4], &W[(size_t)(bn + r) * K + lc4]);
        }
        cp_commit();
    }

    const int niter = K / GBK;
    for (int it = 0; it < niter; it++) {
        const int s = it & 1;
        if (it + 1 < niter) {
            const int k0 = (it + 1) * GBK;
            float* Ad = &As[(s ^ 1) * GST];
            float* Bd = &Bs[(s ^ 1) * GST];
            #pragma unroll
            for (int t = 0; t < 4; t++) {
                int r = lr + t * 32;
                cp_async16(&Ad[r * GLD + lc4], &A[(size_t)(bm + r) * K + k0 + lc4]);
                cp_async16(&Bd[r * GLD + lc4], &W[(size_t)(bn + r) * K + k0 + lc4]);
            }
            cp_commit();
            cp_wait<1>();
        } else {
            cp_wait<0>();
        }
        __syncthreads();

        const float* Ac = &As[s * GST];
        const float* Bc = &Bs[s * GST];
        #pragma unroll
        for (int kk = 0; kk < 4; kk++) {
            const int kd = kk * 8;
            wmma::fragment<wmma::matrix_a, 16, 16, 8, wmma::precision::tf32, wmma::row_major> a0, a1;
            wmma::load_matrix_sync(a0, &Ac[(wr * 32     ) * GLD + kd], GLD);
            wmma::load_matrix_sync(a1, &Ac[(wr * 32 + 16) * GLD + kd], GLD);
            frag_to_tf32(a0); frag_to_tf32(a1);
            #pragma unroll
            for (int nt = 0; nt < 4; nt++) {
                wmma::fragment<wmma::matrix_b, 16, 16, 8, wmma::precision::tf32, wmma::col_major> b;
                wmma::load_matrix_sync(b, &Bc[(wc * 64 + nt * 16) * GLD + kd], GLD);
                frag_to_tf32(b);
                wmma::mma_sync(acc[0][nt], a0, b, acc[0][nt]);
                wmma::mma_sync(acc[1][nt], a1, b, acc[1][nt]);
            }
        }
        __syncthreads();
    }

    #pragma unroll
    for (int i = 0; i < 2; i++)
        #pragma unroll
        for (int j = 0; j < 4; j++) {
            int row = bm + wr * 32 + i * 16;
            int col = bn + wc * 64 + j * 16;
            wmma::store_matrix_sync(&C[(size_t)row * N + col], acc[i][j], N, wmma::mem_row_major);
        }
}

// ---------------------------------------------------------------------------
// RMSNorm + bias + RoPE for q,k; transpose q,k,v into [B,NH,S,D]
// ---------------------------------------------------------------------------
__global__ __launch_bounds__(256)
void normrope_kernel(const float* __restrict__ qlin, const float* __restrict__ klin,
                     const float* __restrict__ vlin,
                     const float* __restrict__ bq, const float* __restrict__ bk,
                     const float* __restrict__ bv,
                     const float* __restrict__ cosT, const float* __restrict__ sinT,
                     const float* __restrict__ w,
                     float* __restrict__ qo, float* __restrict__ ko, float* __restrict__ vo)
{
    const int t = blockIdx.x;
    const int b = t >> 11;
    const int s = t & 2047;
    const int tid = threadIdx.x;

    __shared__ float sq[1024], sk[1024];
    __shared__ float red[16];
    __shared__ float rqs, rks;

    float sumq = 0.f, sumk = 0.f;
    for (int i = tid; i < 1024; i += 256) {
        float x = qlin[(size_t)t * 1024 + i] + bq[i]; sq[i] = x; sumq += x * x;
        float y = klin[(size_t)t * 1024 + i] + bk[i]; sk[i] = y; sumk += y * y;
    }
    #pragma unroll
    for (int off = 16; off > 0; off >>= 1) {
        sumq += __shfl_down_sync(0xffffffffu, sumq, off);
        sumk += __shfl_down_sync(0xffffffffu, sumk, off);
    }
    if ((tid & 31) == 0) { red[tid >> 5] = sumq; red[8 + (tid >> 5)] = sumk; }
    __syncthreads();
    if (tid == 0) {
        float a = 0.f, c = 0.f;
        #pragma unroll
        for (int i2 = 0; i2 < 8; i2++) { a += red[i2]; c += red[8 + i2]; }
        rqs = rsqrtf(a * (1.0f / 1024.0f) + 1e-6f);
        rks = rsqrtf(c * (1.0f / 1024.0f) + 1e-6f);
    }
    __syncthreads();
    const float rq = rqs, rk = rks;

    for (int i = tid; i < 1024; i += 256) {
        int h = i >> 6, d = i & 63;
        float cs = cosT[s * 64 + d], sn = sinT[s * 64 + d];
        int   pi = (d < 32) ? i + 32 : i - 32;
        float sign = (d < 32) ? -1.f : 1.f;
        float wv = w[i], wp = w[pi];
        float qv = sq[i] * rq * wv, qp = sq[pi] * rq * wp;
        float kv = sk[i] * rk * wv, kp = sk[pi] * rk * wp;
        size_t oidx = ((size_t)(b * NHd + h) * SEQ + s) * Dd + d;
        qo[oidx] = qv * cs + sign * qp * sn;
        ko[oidx] = kv * cs + sign * kp * sn;
        vo[oidx] = vlin[(size_t)t * 1024 + i] + bv[i];
    }
}

// ---------------------------------------------------------------------------
// Flash attention, tf32 wmma, NO running-max (scores are O(±10): exp cannot
// overflow fp32) => O lives in persistent accumulator fragments, PV mma
// accumulates directly, single 1/l scale in epilogue.
// Block: 128 queries x 1 (b,h), 8 warps (16 rows each). Scores get +1.0
// on the lower triangle (bias, not mask).
// ---------------------------------------------------------------------------
#define FLD 72
#define FSM_K   (64 * FLD)
#define FSM_S   (128 * FLD)
#define FSM_TOT (2 * FSM_K + FSM_S)     // floats

__global__ __launch_bounds__(256)
void flash_tf32_kernel(const float* __restrict__ q, const float* __restrict__ k,
                       const float* __restrict__ v, float* __restrict__ out)
{
    extern __shared__ __align__(16) float sm[];
    float* Ks = sm;
    float* Vs = sm + FSM_K;
    float* Sp = sm + 2 * FSM_K;          // [128][FLD], warp w owns rows w*16..

    const int tid = threadIdx.x;
    const int w   = tid >> 5;
    const int bh  = blockIdx.y;
    const int qt  = blockIdx.x;          // 128-query tile
    const float* kb = k + (size_t)bh * SEQ * Dd;
    const float* vb = v + (size_t)bh * SEQ * Dd;

    // Q fragments (scaled by 1/8, tf32-rounded)
    wmma::fragment<wmma::matrix_a, 16, 16, 8, wmma::precision::tf32, wmma::row_major> qfrag[8];
    {
        const float* qptr = q + ((size_t)bh * SEQ + qt * 128 + w * 16) * Dd;
        #pragma unroll
        for (int kk = 0; kk < 8; kk++) {
            wmma::load_matrix_sync(qfrag[kk], qptr + kk * 8, Dd);
            #pragma unroll
            for (int e = 0; e < qfrag[kk].num_elements; e++)
                qfrag[kk].x[e] = wmma::__float_to_tf32(qfrag[kk].x[e] * 0.125f);
        }
    }

    // persistent O accumulators: 16 rows x 64 cols per warp
    wmma::fragment<wmma::accumulator, 16, 16, 8, float> oacc[4];
    #pragma unroll
    for (int nt = 0; nt < 4; nt++) wmma::fill_fragment(oacc[nt], 0.0f);

    const int row  = tid >> 1;           // 0..127 (warp-consistent)
    const int half = tid & 1;
    const int qrow = qt * 128 + row;
    float l_priv = 0.f;

    for (int kt = 0; kt < SEQ; kt += 64) {
        __syncthreads();                 // prior Ks/Vs readers done
        #pragma unroll
        for (int t = 0; t < 4; t++) {    // 64x16 float4 per matrix
            int i = t * 256 + tid;
            int r = i >> 4, c = (i & 15) << 2;
            *(float4*)&Ks[r * FLD + c] = *(const float4*)&kb[(size_t)(kt + r) * Dd + c];
            *(float4*)&Vs[r * FLD + c] = *(const float4*)&vb[(size_t)(kt + r) * Dd + c];
        }
        __syncthreads();

        // S = Q @ K^T  (16x64 per warp)
        wmma::fragment<wmma::accumulator, 16, 16, 8, float> sfr[4];
        #pragma unroll
        for (int nt = 0; nt < 4; nt++) wmma::fill_fragment(sfr[nt], 0.0f);
        #pragma unroll
        for (int kk = 0; kk < 8; kk++) {
            const int kd = kk * 8;
            #pragma unroll
            for (int nt = 0; nt < 4; nt++) {
                wmma::fragment<wmma::matrix_b, 16, 16, 8, wmma::precision::tf32, wmma::col_major> bfr;
                wmma::load_matrix_sync(bfr, &Ks[(nt * 16) * FLD + kd], FLD);
                frag_to_tf32(bfr);
                wmma::mma_sync(sfr[nt], qfrag[kk], bfr, sfr[nt]);
            }
        }
        #pragma unroll
        for (int nt = 0; nt < 4; nt++)
            wmma::store_matrix_sync(&Sp[(w * 16) * FLD + nt * 16], sfr[nt], FLD, wmma::mem_row_major);
        __syncwarp();

        // P = exp(S + tril_bias) on own rows; accumulate l
        {
            float* srow = &Sp[row * FLD + half * 32];
            float psum = 0.f;
            #pragma unroll
            for (int c = 0; c < 32; c += 4) {
                float4 s4 = *(float4*)&srow[c];
                int col = kt + half * 32 + c;
                s4.x = __expf(s4.x + ((col + 0) <= qrow ? 1.0f : 0.0f));
                s4.y = __expf(s4.y + ((col + 1) <= qrow ? 1.0f : 0.0f));
                s4.z = __expf(s4.z + ((col + 2) <= qrow ? 1.0f : 0.0f));
                s4.w = __expf(s4.w + ((col + 3) <= qrow ? 1.0f : 0.0f));
                *(float4*)&srow[c] = s4;
                psum += (s4.x + s4.y) + (s4.z + s4.w);
            }
            l_priv += psum;
        }
        __syncwarp();

        // O += P @ V
        #pragma unroll
        for (int kk = 0; kk < 8; kk++) {
            wmma::fragment<wmma::matrix_a, 16, 16, 8, wmma::precision::tf32, wmma::row_major> afr;
            wmma::load_matrix_sync(afr, &Sp[(w * 16) * FLD + kk * 8], FLD);
            frag_to_tf32(afr);
            #pragma unroll
            for (int nt = 0; nt < 4; nt++) {
                wmma::fragment<wmma::matrix_b, 16, 16, 8, wmma::precision::tf32, wmma::row_major> vfr;
                wmma::load_matrix_sync(vfr, &Vs[(kk * 8) * FLD + nt * 16], FLD);
                frag_to_tf32(vfr);
                wmma::mma_sync(oacc[nt], afr, vfr, oacc[nt]);
            }
        }
    }

    // epilogue: O / l, write token-major [B,S,H]
    __syncwarp();
    #pragma unroll
    for (int nt = 0; nt < 4; nt++)
        wmma::store_matrix_sync(&Sp[(w * 16) * FLD + nt * 16], oacc[nt], FLD, wmma::mem_row_major);
    __syncwarp();
    {
        float l_tot = l_priv + __shfl_xor_sync(0xffffffffu, l_priv, 1);
        float invl = 1.f / l_tot;
        const int b = bh >> 4, h = bh & 15;
        const float* orow = &Sp[row * FLD + half * 32];
        float* dst = out + ((size_t)(b * SEQ + qt * 128 + row)) * Hh + h * Dd + half * 32;
        #pragma unroll
        for (int c = 0; c < 32; c += 4) {
            float4 t = *(const float4*)&orow[c];
            t.x *= invl; t.y *= invl; t.z *= invl; t.w *= invl;
            *(float4*)&dst[c] = t;
        }
    }
}

// ---------------------------------------------------------------------------
__global__ __launch_bounds__(256)
void add_bias_kernel(float* __restrict__ out, const float* __restrict__ bo)
{
    int idx = blockIdx.x * 256 + threadIdx.x;
    out[idx] += bo[idx & (Hh - 1)];
}

// ---------------------------------------------------------------------------
extern "C" void kernel_launch(void* const* d_in, const int* in_sizes, int n_in,
                              void* d_out, int out_size)
{
    const float* hs   = (const float*)d_in[0];
    const float* cosT = (const float*)d_in[1];
    const float* sinT = (const float*)d_in[2];
    const float* Wq   = (const float*)d_in[3];
    const float* bq   = (const float*)d_in[4];
    const float* Wk   = (const float*)d_in[5];
    const float* bk   = (const float*)d_in[6];
    const float* Wv   = (const float*)d_in[7];
    const float* bv   = (const float*)d_in[8];
    const float* Wo   = (const float*)d_in[9];
    const float* bo   = (const float*)d_in[10];
    const float* rw   = (const float*)d_in[11];
    float* out = (float*)d_out;

    float* scratch = nullptr;
    cudaGetSymbolAddress((void**)&scratch, g_scratch);
    const size_t SZ = (size_t)Mtok * Hh;
    float* qlin = scratch;
    float* klin = scratch + 1 * SZ;
    float* vlin = scratch + 2 * SZ;
    float* qT   = scratch + 3 * SZ;
    float* kT   = scratch + 4 * SZ;
    float* vT   = scratch + 5 * SZ;
    float* attn = scratch + 6 * SZ;

    const int gemm_smem  = 4 * GST * (int)sizeof(float);          // 81920 B
    const int flash_smem = FSM_TOT * (int)sizeof(float);          // 73728 B
    cudaFuncSetAttribute(gemm_tf32_kernel,
                         cudaFuncAttributeMaxDynamicSharedMemorySize, gemm_smem);
    cudaFuncSetAttribute(flash_tf32_kernel,
                         cudaFuncAttributeMaxDynamicSharedMemorySize, flash_smem);

    dim3 gg(Hh / GBN, Mtok / GBM);
    gemm_tf32_kernel<<<gg, 256, gemm_smem>>>(hs, Wq, qlin, Mtok, Hh, Hh);
    gemm_tf32_kernel<<<gg, 256, gemm_smem>>>(hs, Wk, klin, Mtok, Hh, Hh);
    gemm_tf32_kernel<<<gg, 256, gemm_smem>>>(hs, Wv, vlin, Mtok, Hh, Hh);

    normrope_kernel<<<Mtok, 256>>>(qlin, klin, vlin, bq, bk, bv,
                                   cosT, sinT, rw, qT, kT, vT);

    dim3 fg(SEQ / 128, Bb * NHd);
    flash_tf32_kernel<<<fg, 256, flash_smem>>>(qT, kT, vT, attn);

    gemm_tf32_kernel<<<gg, 256, gemm_smem>>>(attn, Wo, out, Mtok, Hh, Hh);
    add_bias_kernel<<<(Mtok * Hh) / 256, 256>>>(out, bo);
}

// round 4
// speedup vs baseline: 5.9199x; 3.3326x over previous
#include <cuda_runtime.h>
#include <cuda_fp16.h>
#include <mma.h>
#include <math.h>

using namespace nvcuda;

#define Bb    2
#define SEQ   2048
#define Hh    1024
#define NHd   16
#define Dd    64
#define Mtok  4096

// fp32 scratch: qlin,klin,vlin (3 x 4M floats)
__device__ float  g_f32[(size_t)3 * Mtok * Hh];
// half scratch: hs_h(4M) Wq,Wk,Wv,Wo(1M ea) qT,kT,vT(4M ea) attn(4M)
__device__ __half g_f16[(size_t)(4 + 4 + 12 + 4) * 1024 * 1024];

__device__ __forceinline__ void cp_async16(void* smem, const void* gmem) {
    unsigned saddr = (unsigned)__cvta_generic_to_shared(smem);
    asm volatile("cp.async.cg.shared.global [%0], [%1], 16;\n" :: "r"(saddr), "l"(gmem));
}
__device__ __forceinline__ void cp_commit() { asm volatile("cp.async.commit_group;\n"); }
template <int N>
__device__ __forceinline__ void cp_wait() { asm volatile("cp.async.wait_group %0;\n" :: "n"(N)); }

// ---------------------------------------------------------------------------
// fp32 -> fp16 conversion, 4 elems/thread
// ---------------------------------------------------------------------------
__global__ __launch_bounds__(256)
void f2h_kernel(const float* __restrict__ in, __half* __restrict__ out)
{
    int i4 = (blockIdx.x * 256 + threadIdx.x) * 4;
    float4 v = *(const float4*)&in[i4];
    *(__half2*)&out[i4]     = __floats2half2_rn(v.x, v.y);
    *(__half2*)&out[i4 + 2] = __floats2half2_rn(v.z, v.w);
}

// ---------------------------------------------------------------------------
// fp16 GEMM: C[M,N] = A[M,K] @ W[N,K]^T (fp32 accum/out).
// 128x128 tile, BK=32, 2-stage cp.async, 256 threads, 8 warps of 32x64.
// gridDim.z selects (W,C) — used to fuse the 3 QKV projections.
// ---------------------------------------------------------------------------
#define GBM 128
#define GBN 128
#define GBK 32
#define GLDH 40                 // halfs; 80B row stride
#define GSTH (GBM * GLDH)       // halfs per stage per matrix

__global__ __launch_bounds__(256)
void gemm_fp16_kernel(const __half* __restrict__ A,
                      const __half* __restrict__ W0, const __half* __restrict__ W1,
                      const __half* __restrict__ W2,
                      float* __restrict__ C0, float* __restrict__ C1, float* __restrict__ C2,
                      int M, int N, int K)
{
    __shared__ __align__(16) __half As[2 * GSTH];
    __shared__ __align__(16) __half Bs[2 * GSTH];

    const __half* W = (blockIdx.z == 0) ? W0 : (blockIdx.z == 1) ? W1 : W2;
    float*        C = (blockIdx.z == 0) ? C0 : (blockIdx.z == 1) ? C1 : C2;

    const int tid = threadIdx.x;
    const int bm = blockIdx.y * GBM, bn = blockIdx.x * GBN;
    const int w  = tid >> 5;
    const int wr = w & 3;
    const int wc = w >> 2;

    wmma::fragment<wmma::accumulator, 16, 16, 16, float> acc[2][4];
    #pragma unroll
    for (int i = 0; i < 2; i++)
        #pragma unroll
        for (int j = 0; j < 4; j++) wmma::fill_fragment(acc[i][j], 0.0f);

    const int lr  = tid >> 2;             // 0..63
    const int lc8 = (tid & 3) << 3;       // 0,8,16,24

    // prefetch stage 0 (each thread: 2 rows of A, 2 rows of W)
    #pragma unroll
    for (int t = 0; t < 2; t++) {
        int r = lr + t * 64;
        cp_async16(&As[r * GLDH + lc8], &A[(size_t)(bm + r) * K + lc8]);
        cp_async16(&Bs[r * GLDH + lc8], &W[(size_t)(bn + r) * K + lc8]);
    }
    cp_commit();

    const int niter = K / GBK;
    for (int it = 0; it < niter; it++) {
        const int s = it & 1;
        if (it + 1 < niter) {
            const int k0 = (it + 1) * GBK;
            __half* Ad = &As[(s ^ 1) * GSTH];
            __half* Bd = &Bs[(s ^ 1) * GSTH];
            #pragma unroll
            for (int t = 0; t < 2; t++) {
                int r = lr + t * 64;
                cp_async16(&Ad[r * GLDH + lc8], &A[(size_t)(bm + r) * K + k0 + lc8]);
                cp_async16(&Bd[r * GLDH + lc8], &W[(size_t)(bn + r) * K + k0 + lc8]);
            }
            cp_commit();
            cp_wait<1>();
        } else {
            cp_wait<0>();
        }
        __syncthreads();

        const __half* Ac = &As[s * GSTH];
        const __half* Bc = &Bs[s * GSTH];
        #pragma unroll
        for (int kk = 0; kk < 2; kk++) {
            const int kd = kk * 16;
            wmma::fragment<wmma::matrix_a, 16, 16, 16, __half, wmma::row_major> a0, a1;
            wmma::load_matrix_sync(a0, &Ac[(wr * 32     ) * GLDH + kd], GLDH);
            wmma::load_matrix_sync(a1, &Ac[(wr * 32 + 16) * GLDH + kd], GLDH);
            #pragma unroll
            for (int nt = 0; nt < 4; nt++) {
                wmma::fragment<wmma::matrix_b, 16, 16, 16, __half, wmma::col_major> b;
                wmma::load_matrix_sync(b, &Bc[(wc * 64 + nt * 16) * GLDH + kd], GLDH);
                wmma::mma_sync(acc[0][nt], a0, b, acc[0][nt]);
                wmma::mma_sync(acc[1][nt], a1, b, acc[1][nt]);
            }
        }
        __syncthreads();
    }

    #pragma unroll
    for (int i = 0; i < 2; i++)
        #pragma unroll
        for (int j = 0; j < 4; j++) {
            int row = bm + wr * 32 + i * 16;
            int col = bn + wc * 64 + j * 16;
            wmma::store_matrix_sync(&C[(size_t)row * N + col], acc[i][j], N, wmma::mem_row_major);
        }
}

// ---------------------------------------------------------------------------
// RMSNorm + bias + RoPE; outputs HALF q/k/v in [B,NH,S,D]; q pre-scaled 1/8.
// ---------------------------------------------------------------------------
__global__ __launch_bounds__(256)
void normrope_kernel(const float* __restrict__ qlin, const float* __restrict__ klin,
                     const float* __restrict__ vlin,
                     const float* __restrict__ bq, const float* __restrict__ bk,
                     const float* __restrict__ bv,
                     const float* __restrict__ cosT, const float* __restrict__ sinT,
                     const float* __restrict__ w,
                     __half* __restrict__ qo, __half* __restrict__ ko, __half* __restrict__ vo)
{
    const int t = blockIdx.x;
    const int b = t >> 11;
    const int s = t & 2047;
    const int tid = threadIdx.x;

    __shared__ float sq[1024], sk[1024];
    __shared__ float red[16];
    __shared__ float rqs, rks;

    float sumq = 0.f, sumk = 0.f;
    for (int i = tid; i < 1024; i += 256) {
        float x = qlin[(size_t)t * 1024 + i] + bq[i]; sq[i] = x; sumq += x * x;
        float y = klin[(size_t)t * 1024 + i] + bk[i]; sk[i] = y; sumk += y * y;
    }
    #pragma unroll
    for (int off = 16; off > 0; off >>= 1) {
        sumq += __shfl_down_sync(0xffffffffu, sumq, off);
        sumk += __shfl_down_sync(0xffffffffu, sumk, off);
    }
    if ((tid & 31) == 0) { red[tid >> 5] = sumq; red[8 + (tid >> 5)] = sumk; }
    __syncthreads();
    if (tid == 0) {
        float a = 0.f, c = 0.f;
        #pragma unroll
        for (int i2 = 0; i2 < 8; i2++) { a += red[i2]; c += red[8 + i2]; }
        rqs = rsqrtf(a * (1.0f / 1024.0f) + 1e-6f);
        rks = rsqrtf(c * (1.0f / 1024.0f) + 1e-6f);
    }
    __syncthreads();
    const float rq = rqs, rk = rks;

    for (int i = tid; i < 1024; i += 256) {
        int h = i >> 6, d = i & 63;
        float cs = cosT[s * 64 + d], sn = sinT[s * 64 + d];
        int   pi = (d < 32) ? i + 32 : i - 32;
        float sign = (d < 32) ? -1.f : 1.f;
        float wv = w[i], wp = w[pi];
        float qv = sq[i] * rq * wv, qp = sq[pi] * rq * wp;
        float kv = sk[i] * rk * wv, kp = sk[pi] * rk * wp;
        size_t oidx = ((size_t)(b * NHd + h) * SEQ + s) * Dd + d;
        qo[oidx] = __float2half((qv * cs + sign * qp * sn) * 0.125f);
        ko[oidx] = __float2half(kv * cs + sign * kp * sn);
        vo[oidx] = __float2half(vlin[(size_t)t * 1024 + i] + bv[i]);
    }
}

// ---------------------------------------------------------------------------
// Flash attention, fp16 wmma, no running max (|scores| <= 9; exp(s+1-3)
// bounded, constant -3 shift cancels in O = P@V / l exactly).
// Block: 128 queries x 1 (b,h), 8 warps. +1.0 tril bias (NOT a mask).
// ---------------------------------------------------------------------------
#define FLDH 72                         // half row stride for Ks/Vs/Ph
#define FLDS 72                         // float row stride for Sp
#define FSM_BYTES (2*(64*FLDH*2) + 128*FLDS*4 + 128*FLDH*2)

__global__ __launch_bounds__(256)
void flash_fp16_kernel(const __half* __restrict__ q, const __half* __restrict__ k,
                       const __half* __restrict__ v, __half* __restrict__ out)
{
    extern __shared__ __align__(16) char smraw[];
    __half* Ks = (__half*)smraw;                       // [64][FLDH]
    __half* Vs = Ks + 64 * FLDH;                       // [64][FLDH]
    float*  Sp = (float*)(Vs + 64 * FLDH);             // [128][FLDS]
    __half* Ph = (__half*)(Sp + 128 * FLDS);           // [128][FLDH]

    const int tid = threadIdx.x;
    const int w   = tid >> 5;
    const int bh  = blockIdx.y;
    const int qt  = blockIdx.x;
    const __half* kb = k + (size_t)bh * SEQ * Dd;
    const __half* vb = v + (size_t)bh * SEQ * Dd;

    // Q fragments (already scaled by 1/8 in normrope)
    wmma::fragment<wmma::matrix_a, 16, 16, 16, __half, wmma::row_major> qfrag[4];
    {
        const __half* qptr = q + ((size_t)bh * SEQ + qt * 128 + w * 16) * Dd;
        #pragma unroll
        for (int kk = 0; kk < 4; kk++)
            wmma::load_matrix_sync(qfrag[kk], qptr + kk * 16, Dd);
    }

    wmma::fragment<wmma::accumulator, 16, 16, 16, float> oacc[4];
    #pragma unroll
    for (int nt = 0; nt < 4; nt++) wmma::fill_fragment(oacc[nt], 0.0f);

    const int row  = tid >> 1;           // 0..127
    const int half = tid & 1;
    const int qrow = qt * 128 + row;
    float l_priv = 0.f;

    for (int kt = 0; kt < SEQ; kt += 64) {
        __syncthreads();
        #pragma unroll
        for (int t = 0; t < 2; t++) {    // 64 rows x 64 halfs = 512 x 16B per matrix
            int i = t * 256 + tid;
            int r = i >> 3, c8 = (i & 7) << 3;
            *(float4*)&Ks[r * FLDH + c8] = *(const float4*)&kb[(size_t)(kt + r) * Dd + c8];
            *(float4*)&Vs[r * FLDH + c8] = *(const float4*)&vb[(size_t)(kt + r) * Dd + c8];
        }
        __syncthreads();

        // S = Q @ K^T (16x64 per warp)
        wmma::fragment<wmma::accumulator, 16, 16, 16, float> sfr[4];
        #pragma unroll
        for (int nt = 0; nt < 4; nt++) wmma::fill_fragment(sfr[nt], 0.0f);
        #pragma unroll
        for (int kk = 0; kk < 4; kk++) {
            const int kd = kk * 16;
            #pragma unroll
            for (int nt = 0; nt < 4; nt++) {
                wmma::fragment<wmma::matrix_b, 16, 16, 16, __half, wmma::col_major> bfr;
                wmma::load_matrix_sync(bfr, &Ks[(nt * 16) * FLDH + kd], FLDH);
                wmma::mma_sync(sfr[nt], qfrag[kk], bfr, sfr[nt]);
            }
        }
        #pragma unroll
        for (int nt = 0; nt < 4; nt++)
            wmma::store_matrix_sync(&Sp[(w * 16) * FLDS + nt * 16], sfr[nt], FLDS, wmma::mem_row_major);
        __syncwarp();

        // P = exp(S + tril - 3) -> half; accumulate l
        {
            float*  srow = &Sp[row * FLDS + half * 32];
            __half* prow = &Ph[row * FLDH + half * 32];
            float psum = 0.f;
            #pragma unroll
            for (int c = 0; c < 32; c += 4) {
                float4 s4 = *(float4*)&srow[c];
                int col = kt + half * 32 + c;
                float p0 = __expf(s4.x - 3.0f + ((col + 0) <= qrow ? 1.0f : 0.0f));
                float p1 = __expf(s4.y - 3.0f + ((col + 1) <= qrow ? 1.0f : 0.0f));
                float p2 = __expf(s4.z - 3.0f + ((col + 2) <= qrow ? 1.0f : 0.0f));
                float p3 = __expf(s4.w - 3.0f + ((col + 3) <= qrow ? 1.0f : 0.0f));
                *(__half2*)&prow[c]     = __floats2half2_rn(p0, p1);
                *(__half2*)&prow[c + 2] = __floats2half2_rn(p2, p3);
                psum += (p0 + p1) + (p2 + p3);
            }
            l_priv += psum;
        }
        __syncwarp();

        // O += P @ V
        #pragma unroll
        for (int kk = 0; kk < 4; kk++) {
            wmma::fragment<wmma::matrix_a, 16, 16, 16, __half, wmma::row_major> afr;
            wmma::load_matrix_sync(afr, &Ph[(w * 16) * FLDH + kk * 16], FLDH);
            #pragma unroll
            for (int nt = 0; nt < 4; nt++) {
                wmma::fragment<wmma::matrix_b, 16, 16, 16, __half, wmma::row_major> vfr;
                wmma::load_matrix_sync(vfr, &Vs[(kk * 16) * FLDH + nt * 16], FLDH);
                wmma::mma_sync(oacc[nt], afr, vfr, oacc[nt]);
            }
        }
    }

    // epilogue: O / l -> half, token-major [B,S,H]
    __syncwarp();
    #pragma unroll
    for (int nt = 0; nt < 4; nt++)
        wmma::store_matrix_sync(&Sp[(w * 16) * FLDS + nt * 16], oacc[nt], FLDS, wmma::mem_row_major);
    __syncwarp();
    {
        float l_tot = l_priv + __shfl_xor_sync(0xffffffffu, l_priv, 1);
        float invl = 1.f / l_tot;
        const int b = bh >> 4, h = bh & 15;
        const float* orow = &Sp[row * FLDS + half * 32];
        __half* dst = out + ((size_t)(b * SEQ + qt * 128 + row)) * Hh + h * Dd + half * 32;
        #pragma unroll
        for (int c = 0; c < 32; c += 4) {
            float4 t = *(const float4*)&orow[c];
            *(__half2*)&dst[c]     = __floats2half2_rn(t.x * invl, t.y * invl);
            *(__half2*)&dst[c + 2] = __floats2half2_rn(t.z * invl, t.w * invl);
        }
    }
}

// ---------------------------------------------------------------------------
__global__ __launch_bounds__(256)
void add_bias_kernel(float* __restrict__ out, const float* __restrict__ bo)
{
    int idx = blockIdx.x * 256 + threadIdx.x;
    out[idx] += bo[idx & (Hh - 1)];
}

// ---------------------------------------------------------------------------
extern "C" void kernel_launch(void* const* d_in, const int* in_sizes, int n_in,
                              void* d_out, int out_size)
{
    const float* hs   = (const float*)d_in[0];
    const float* cosT = (const float*)d_in[1];
    const float* sinT = (const float*)d_in[2];
    const float* Wq   = (const float*)d_in[3];
    const float* bq   = (const float*)d_in[4];
    const float* Wk   = (const float*)d_in[5];
    const float* bk   = (const float*)d_in[6];
    const float* Wv   = (const float*)d_in[7];
    const float* bv   = (const float*)d_in[8];
    const float* Wo   = (const float*)d_in[9];
    const float* bo   = (const float*)d_in[10];
    const float* rw   = (const float*)d_in[11];
    float* out = (float*)d_out;

    float* f32 = nullptr;  cudaGetSymbolAddress((void**)&f32, g_f32);
    __half* f16 = nullptr; cudaGetSymbolAddress((void**)&f16, g_f16);

    const size_t SZ = (size_t)Mtok * Hh;       // 4M
    const size_t WZ = (size_t)Hh * Hh;         // 1M
    float* qlin = f32;
    float* klin = f32 + SZ;
    float* vlin = f32 + 2 * SZ;

    __half* hs_h  = f16;
    __half* Wq_h  = f16 + 4 * WZ;              // after 4M hs
    __half* Wk_h  = Wq_h + WZ;
    __half* Wv_h  = Wk_h + WZ;
    __half* Wo_h  = Wv_h + WZ;
    __half* qT    = Wo_h + WZ;
    __half* kT    = qT + SZ;
    __half* vT    = kT + SZ;
    __half* attn  = vT + SZ;

    cudaFuncSetAttribute(flash_fp16_kernel,
                         cudaFuncAttributeMaxDynamicSharedMemorySize, FSM_BYTES);

    f2h_kernel<<<(int)(SZ / 1024), 256>>>(hs, hs_h);
    f2h_kernel<<<(int)(WZ / 1024), 256>>>(Wq, Wq_h);
    f2h_kernel<<<(int)(WZ / 1024), 256>>>(Wk, Wk_h);
    f2h_kernel<<<(int)(WZ / 1024), 256>>>(Wv, Wv_h);
    f2h_kernel<<<(int)(WZ / 1024), 256>>>(Wo, Wo_h);

    dim3 gqkv(Hh / GBN, Mtok / GBM, 3);
    gemm_fp16_kernel<<<gqkv, 256>>>(hs_h, Wq_h, Wk_h, Wv_h,
                                    qlin, klin, vlin, Mtok, Hh, Hh);

    normrope_kernel<<<Mtok, 256>>>(qlin, klin, vlin, bq, bk, bv,
                                   cosT, sinT, rw, qT, kT, vT);

    dim3 fg(SEQ / 128, Bb * NHd);
    flash_fp16_kernel<<<fg, 256, FSM_BYTES>>>(qT, kT, vT, attn);

    dim3 gout(Hh / GBN, Mtok / GBM, 1);
    gemm_fp16_kernel<<<gout, 256>>>(attn, Wo_h, Wo_h, Wo_h,
                                    out, out, out, Mtok, Hh, Hh);
    add_bias_kernel<<<(int)(SZ / 256), 256>>>(out, bo);
}